// round 4
// baseline (speedup 1.0000x reference)
#include <cuda_runtime.h>
#include <math.h>

#define NROWS 4096
#define HALF  2048
#define DDIM  256

// Scratch (no device allocation allowed in kernel_launch)
__device__ float g_norms[3 * NROWS];
__device__ float g_rowloss[NROWS];

__device__ __forceinline__ float warp_sum(float v) {
#pragma unroll
    for (int o = 16; o; o >>= 1) v += __shfl_xor_sync(0xFFFFFFFFu, v, o);
    return v;
}

// ---------------- kernel 1: squared row norms for all 3 features ------------
__global__ void norms_kernel(const float* __restrict__ f0,
                             const float* __restrict__ f1,
                             const float* __restrict__ f2) {
    int w    = (blockIdx.x * blockDim.x + threadIdx.x) >> 5;
    int lane = threadIdx.x & 31;
    if (w >= 3 * NROWS) return;
    const float* F = (w < NROWS) ? f0 : (w < 2 * NROWS) ? f1 : f2;
    int row = (w >= 2 * NROWS) ? (w - 2 * NROWS) : (w >= NROWS ? w - NROWS : w);
    const float4* R = (const float4*)(F + (size_t)row * DDIM);
    float4 a = R[lane], b = R[lane + 32];
    float s = a.x*a.x + a.y*a.y + a.z*a.z + a.w*a.w
            + b.x*b.x + b.y*b.y + b.z*b.z + b.w*b.w;
    s = warp_sum(s);
    if (lane == 0) g_norms[w] = s;
}

// ---------------- scalar helpers -------------------------------------------
__device__ __forceinline__ float logaddexp_f(float a, float b) {
    float m = fmaxf(a, b), n = fminf(a, b);
    return m + log1pf(expf(n - m));
}

// torchsort soft_rank (KL reg) for a row of length 4, strength = 2.0.
// Implements the reference's min-max dual formula literally.
__device__ void soft_rank4(const float v[4], float out[4]) {
    float s[4];
    int perm[4] = {0, 1, 2, 3};
#pragma unroll
    for (int t = 0; t < 4; ++t) s[t] = v[t] * 0.5f;  // theta = v / strength

    // sort descending (network), track permutation
#define CSWAP(x, y)                                                     \
    if (s[x] < s[y]) {                                                  \
        float tf = s[x]; s[x] = s[y]; s[y] = tf;                        \
        int   ti = perm[x]; perm[x] = perm[y]; perm[y] = ti;            \
    }
    CSWAP(0, 1) CSWAP(2, 3) CSWAP(0, 2) CSWAP(1, 3) CSWAP(1, 2)
#undef CSWAP

    // lse over segments s[i..j]
    float lse_s[4][4];
#pragma unroll
    for (int i = 0; i < 4; ++i) {
        float L = s[i];
        lse_s[i][i] = L;
#pragma unroll
        for (int j = i + 1; j < 4; ++j) {
            L = logaddexp_f(L, s[j]);
            lse_s[i][j] = L;
        }
    }

    // log of segment sums of w = [4,3,2,1]
    const float LW00 = 1.38629436f, LW01 = 1.94591015f, LW02 = 2.19722458f, LW03 = 2.30258509f;
    const float LW11 = 1.09861229f, LW12 = 1.60943791f, LW13 = 1.79175947f;
    const float LW22 = 0.69314718f, LW23 = 1.09861229f;
    const float LW33 = 0.0f;

    float B[4][4];
    B[0][0] = lse_s[0][0] - LW00; B[0][1] = lse_s[0][1] - LW01;
    B[0][2] = lse_s[0][2] - LW02; B[0][3] = lse_s[0][3] - LW03;
    B[1][1] = lse_s[1][1] - LW11; B[1][2] = lse_s[1][2] - LW12;
    B[1][3] = lse_s[1][3] - LW13;
    B[2][2] = lse_s[2][2] - LW22; B[2][3] = lse_s[2][3] - LW23;
    B[3][3] = lse_s[3][3] - LW33;

    // suffix max over j (for j >= i)
    float M[4][4];
#pragma unroll
    for (int i = 0; i < 4; ++i) {
        M[i][3] = B[i][3];
#pragma unroll
        for (int j = 2; j >= 0; --j)
            if (j >= i) M[i][j] = fmaxf(B[i][j], M[i][j + 1]);
    }

    // dual[k] = min_{i<=k} M[i][k]
    float dual[4];
    dual[0] = M[0][0];
    dual[1] = fminf(M[0][1], M[1][1]);
    dual[2] = fminf(fminf(M[0][2], M[1][2]), M[2][2]);
    dual[3] = fminf(fminf(M[0][3], M[1][3]), fminf(M[2][3], M[3][3]));

#pragma unroll
    for (int k = 0; k < 4; ++k) out[perm[k]] = expf(s[k] - dual[k]);
}

__device__ __forceinline__ float spearman4(const float a[4], const float b[4]) {
    float ma = 0.25f * (a[0] + a[1] + a[2] + a[3]);
    float mb = 0.25f * (b[0] + b[1] + b[2] + b[3]);
    float na = 0.f, nb = 0.f, dp = 0.f;
#pragma unroll
    for (int t = 0; t < 4; ++t) {
        float x = a[t] - ma, y = b[t] - mb;
        na += x * x; nb += y * y; dp += x * y;
    }
    return dp * rsqrtf(na) * rsqrtf(nb);
}

// ---------------- kernel 2: per-row loss (one warp per row) ----------------
__global__ void rowloss_kernel(const float* __restrict__ f0,
                               const float* __restrict__ f1,
                               const float* __restrict__ f2) {
    int i    = (blockIdx.x * blockDim.x + threadIdx.x) >> 5;
    int lane = threadIdx.x & 31;
    if (i >= NROWS) return;

    // analytic positive set: 4 partners in the opposite half, same id
    int p    = (i & (HALF - 1)) >> 2;
    int base = (i < HALF) ? (HALF + 4 * p) : (4 * p);

    const float* Fs[3] = {f0, f1, f2};
    float r[3][4];

#pragma unroll
    for (int f = 0; f < 3; ++f) {
        const float4* Ri = (const float4*)(Fs[f] + (size_t)i * DDIM);
        float4 a0 = Ri[lane], a1 = Ri[lane + 32];
        float sqi = g_norms[f * NROWS + i];
        float dist[4];
#pragma unroll
        for (int k = 0; k < 4; ++k) {
            const float4* Rj = (const float4*)(Fs[f] + (size_t)(base + k) * DDIM);
            float4 b0 = Rj[lane], b1 = Rj[lane + 32];
            float dp = a0.x*b0.x + a0.y*b0.y + a0.z*b0.z + a0.w*b0.w
                     + a1.x*b1.x + a1.y*b1.y + a1.z*b1.z + a1.w*b1.w;
            dp = warp_sum(dp);  // all lanes hold full dot
            float d2 = sqi + g_norms[f * NROWS + base + k] - 2.0f * dp;
            dist[k] = sqrtf(fmaxf(d2, 1e-12f));
        }
        soft_rank4(dist, r[f]);  // all lanes compute redundantly (no divergence)
    }

    if (lane == 0) {
        float c01 = spearman4(r[0], r[1]);
        float c02 = spearman4(r[0], r[2]);
        float c12 = spearman4(r[1], r[2]);
        g_rowloss[i] = (c01 + c02 + c12 + 3.0f) * (1.0f / 6.0f);
    }
}

// ---------------- kernel 3: deterministic mean -----------------------------
__global__ void reduce_kernel(float* __restrict__ out) {
    __shared__ float sh[512];
    int t = threadIdx.x;
    float s = 0.f;
    for (int idx = t; idx < NROWS; idx += 512) s += g_rowloss[idx];
    sh[t] = s;
    __syncthreads();
#pragma unroll
    for (int o = 256; o; o >>= 1) {
        if (t < o) sh[t] += sh[t + o];
        __syncthreads();
    }
    if (t == 0) out[0] = sh[0] * (1.0f / NROWS);
}

extern "C" void kernel_launch(void* const* d_in, const int* in_sizes, int n_in,
                              void* d_out, int out_size) {
    const float* f0 = (const float*)d_in[0];
    const float* f1 = (const float*)d_in[1];
    const float* f2 = (const float*)d_in[2];
    (void)in_sizes; (void)n_in; (void)out_size;

    // 3*4096 warps for norms
    norms_kernel<<<(3 * NROWS * 32 + 255) / 256, 256>>>(f0, f1, f2);
    // 4096 warps, one per row
    rowloss_kernel<<<(NROWS * 32) / 256, 256>>>(f0, f1, f2);
    // single-block deterministic reduction
    reduce_kernel<<<1, 512>>>((float*)d_out);
}

// round 8
// speedup vs baseline: 1.7700x; 1.7700x over previous
#include <cuda_runtime.h>
#include <math.h>

#define NROWS  4096
#define HALF   2048
#define DDIM   256
#define GROUPS 512   // NROWS / 8

__device__ float g_groupsum[GROUPS];

__device__ __forceinline__ float warp_sum(float v) {
#pragma unroll
    for (int o = 16; o; o >>= 1) v += __shfl_xor_sync(0xFFFFFFFFu, v, o);
    return v;
}

__device__ __forceinline__ float logaddexp_f(float a, float b) {
    float m = fmaxf(a, b), n = fminf(a, b);
    return m + log1pf(expf(n - m));
}

// torchsort soft_rank (KL reg), row length 4, strength = 2.0.
// Literal implementation of the reference's min-max dual formula.
__device__ void soft_rank4(const float v[4], float out[4]) {
    float s[4];
    int perm[4] = {0, 1, 2, 3};
#pragma unroll
    for (int t = 0; t < 4; ++t) s[t] = v[t] * 0.5f;  // theta = v / strength

#define CSWAP(x, y)                                                     \
    if (s[x] < s[y]) {                                                  \
        float tf = s[x]; s[x] = s[y]; s[y] = tf;                        \
        int   ti = perm[x]; perm[x] = perm[y]; perm[y] = ti;            \
    }
    CSWAP(0, 1) CSWAP(2, 3) CSWAP(0, 2) CSWAP(1, 3) CSWAP(1, 2)
#undef CSWAP

    float lse_s[4][4];
#pragma unroll
    for (int i = 0; i < 4; ++i) {
        float L = s[i];
        lse_s[i][i] = L;
#pragma unroll
        for (int j = i + 1; j < 4; ++j) {
            L = logaddexp_f(L, s[j]);
            lse_s[i][j] = L;
        }
    }

    const float LW00 = 1.38629436f, LW01 = 1.94591015f, LW02 = 2.19722458f, LW03 = 2.30258509f;
    const float LW11 = 1.09861229f, LW12 = 1.60943791f, LW13 = 1.79175947f;
    const float LW22 = 0.69314718f, LW23 = 1.09861229f;
    const float LW33 = 0.0f;

    float B[4][4];
    B[0][0] = lse_s[0][0] - LW00; B[0][1] = lse_s[0][1] - LW01;
    B[0][2] = lse_s[0][2] - LW02; B[0][3] = lse_s[0][3] - LW03;
    B[1][1] = lse_s[1][1] - LW11; B[1][2] = lse_s[1][2] - LW12;
    B[1][3] = lse_s[1][3] - LW13;
    B[2][2] = lse_s[2][2] - LW22; B[2][3] = lse_s[2][3] - LW23;
    B[3][3] = lse_s[3][3] - LW33;

    float M[4][4];
#pragma unroll
    for (int i = 0; i < 4; ++i) {
        M[i][3] = B[i][3];
#pragma unroll
        for (int j = 2; j >= 0; --j)
            if (j >= i) M[i][j] = fmaxf(B[i][j], M[i][j + 1]);
    }

    float dual[4];
    dual[0] = M[0][0];
    dual[1] = fminf(M[0][1], M[1][1]);
    dual[2] = fminf(fminf(M[0][2], M[1][2]), M[2][2]);
    dual[3] = fminf(fminf(M[0][3], M[1][3]), fminf(M[2][3], M[3][3]));

#pragma unroll
    for (int k = 0; k < 4; ++k) out[perm[k]] = expf(s[k] - dual[k]);
}

__device__ __forceinline__ float spearman4(const float a[4], const float b[4]) {
    float ma = 0.25f * (a[0] + a[1] + a[2] + a[3]);
    float mb = 0.25f * (b[0] + b[1] + b[2] + b[3]);
    float na = 0.f, nb = 0.f, dp = 0.f;
#pragma unroll
    for (int t = 0; t < 4; ++t) {
        float x = a[t] - ma, y = b[t] - mb;
        na += x * x; nb += y * y; dp += x * y;
    }
    return dp * rsqrtf(na) * rsqrtf(nb);
}

// ---------------- main kernel: one block per id-group of 8 rows ------------
// Group p owns rows {4p..4p+3} (half A) and {2048+4p..2048+4p+3} (half B).
// All 8 rows' positive-set distances are the 4x4 A-B cross-distance matrix.
__global__ __launch_bounds__(256) void group_kernel(const float* __restrict__ f0,
                                                    const float* __restrict__ f1,
                                                    const float* __restrict__ f2) {
    __shared__ float sh[3][8][DDIM];   // 24 KB: 8 rows x 3 features
    __shared__ float dist[3][4][4];    // dist[f][i][j] = ||A_i - B_j||
    __shared__ float rloss[8];

    int p    = blockIdx.x;
    int tid  = threadIdx.x;
    int w    = tid >> 5;
    int lane = tid & 31;

    const float* Fs[3] = {f0, f1, f2};

    // Load 1536 float4 (24 KB), 6 per thread, coalesced per row-chunk.
#pragma unroll
    for (int u = 0; u < 6; ++u) {
        int idx = tid + u * 256;          // 0..1535
        int f   = idx >> 9;               // 512 float4 per feature
        int rem = idx & 511;
        int r   = rem >> 6;               // local row 0..7
        int c   = rem & 63;               // float4 column 0..63
        int grow = (r < 4) ? (4 * p + r) : (HALF + 4 * p + (r - 4));
        float4 v = ((const float4*)(Fs[f] + (size_t)grow * DDIM))[c];
        ((float4*)&sh[f][r][0])[c] = v;
    }
    __syncthreads();

    // 48 dots (3 features x 4x4 pairs), 6 per warp. Direct sum of squared diffs.
#pragma unroll
    for (int t = 0; t < 6; ++t) {
        int d = w * 6 + t;
        int f = d >> 4, pair = d & 15, i = pair >> 2, j = pair & 3;
        const float4* A = (const float4*)&sh[f][i][0];
        const float4* B = (const float4*)&sh[f][4 + j][0];
        float4 a0 = A[lane], a1 = A[lane + 32];
        float4 b0 = B[lane], b1 = B[lane + 32];
        float dx0 = a0.x - b0.x, dy0 = a0.y - b0.y, dz0 = a0.z - b0.z, dw0 = a0.w - b0.w;
        float dx1 = a1.x - b1.x, dy1 = a1.y - b1.y, dz1 = a1.z - b1.z, dw1 = a1.w - b1.w;
        float s = dx0*dx0 + dy0*dy0 + dz0*dz0 + dw0*dw0
                + dx1*dx1 + dy1*dy1 + dz1*dz1 + dw1*dw1;
        s = warp_sum(s);
        if (lane == 0) dist[f][i][j] = sqrtf(fmaxf(s, 1e-12f));
    }
    __syncthreads();

    // Per-row tail: warp w owns local row w. Lanes 0-2 run the 3 soft-ranks
    // in parallel; shfl-gather; lane 0 does spearman.
    {
        int f = (lane < 3) ? lane : 0;
        float v[4], rr[4];
#pragma unroll
        for (int k = 0; k < 4; ++k)
            v[k] = (w < 4) ? dist[f][w][k] : dist[f][k][w - 4];
        soft_rank4(v, rr);

        float r0[4], r1[4], r2[4];
#pragma unroll
        for (int k = 0; k < 4; ++k) {
            r0[k] = __shfl_sync(0xFFFFFFFFu, rr[k], 0);
            r1[k] = __shfl_sync(0xFFFFFFFFu, rr[k], 1);
            r2[k] = __shfl_sync(0xFFFFFFFFu, rr[k], 2);
        }
        if (lane == 0) {
            float c01 = spearman4(r0, r1);
            float c02 = spearman4(r0, r2);
            float c12 = spearman4(r1, r2);
            rloss[w] = (c01 + c02 + c12 + 3.0f) * (1.0f / 6.0f);
        }
    }
    __syncthreads();

    if (tid == 0) {
        float s = rloss[0] + rloss[1] + rloss[2] + rloss[3]
                + rloss[4] + rloss[5] + rloss[6] + rloss[7];
        g_groupsum[p] = s;
    }
}

// ---------------- deterministic final mean ---------------------------------
__global__ void reduce_kernel(float* __restrict__ out) {
    __shared__ float sh[512];
    int t = threadIdx.x;
    sh[t] = g_groupsum[t];
    __syncthreads();
#pragma unroll
    for (int o = 256; o; o >>= 1) {
        if (t < o) sh[t] += sh[t + o];
        __syncthreads();
    }
    if (t == 0) out[0] = sh[0] * (1.0f / NROWS);
}

extern "C" void kernel_launch(void* const* d_in, const int* in_sizes, int n_in,
                              void* d_out, int out_size) {
    const float* f0 = (const float*)d_in[0];
    const float* f1 = (const float*)d_in[1];
    const float* f2 = (const float*)d_in[2];
    (void)in_sizes; (void)n_in; (void)out_size;

    group_kernel<<<GROUPS, 256>>>(f0, f1, f2);
    reduce_kernel<<<1, 512>>>((float*)d_out);
}